// round 9
// baseline (speedup 1.0000x reference)
#include <cuda_runtime.h>
#include <cuda_bf16.h>
#include <cstdint>

#define D3 384
#define MT 2047          // nodes per tree
#define NT 32
#define NN 65504         // 32 * 2047
#define NINT 32736       // 32 * 1023 internal nodes
#define SA 136           // smem row stride in bf16 (272B) -> ldmatrix conflict-free

// ------------------------- device scratch ----------------------------------
__device__ float g_wxiou[NN * D3];      // W_iou*x + b_iou (internal nodes only)
__device__ float g_wxf[NN * 128];       // W_f*x + b_f, internal nodes
__device__ float g_c[NN * 128];         // cell state
__device__ float g_fc[NN * 128];        // f(child)*c(child) (CTA-local use)
__device__ unsigned g_counts[32];       // global barrier slots (reset by k_cvt)

__device__ __align__(16) __nv_bfloat16 g_Wiou_h[D3 * 128];
__device__ __align__(16) __nv_bfloat16 g_Wiou_l[D3 * 128];
__device__ __align__(16) __nv_bfloat16 g_Uiou_h[D3 * 128];
__device__ __align__(16) __nv_bfloat16 g_Uiou_l[D3 * 128];
__device__ __align__(16) __nv_bfloat16 g_Wf_h[128 * 128];
__device__ __align__(16) __nv_bfloat16 g_Wf_l[128 * 128];
__device__ __align__(16) __nv_bfloat16 g_Uf_h[128 * 128];
__device__ __align__(16) __nv_bfloat16 g_Uf_l[128 * 128];

__device__ __forceinline__ float sigf(float x) {
    return 1.0f / (1.0f + __expf(-x));
}
__device__ __forceinline__ float tanhfast(float x) {
    return 1.0f - 2.0f / (__expf(2.0f * x) + 1.0f);
}

// ------------------------- mma / ldmatrix helpers ---------------------------
__device__ __forceinline__ void ldsm4(uint32_t addr, uint32_t* r) {
    asm volatile("ldmatrix.sync.aligned.m8n8.x4.shared.b16 {%0,%1,%2,%3}, [%4];"
                 : "=r"(r[0]), "=r"(r[1]), "=r"(r[2]), "=r"(r[3]) : "r"(addr));
}
__device__ __forceinline__ void mma16816(float* c, const uint32_t* a,
                                         uint32_t b0, uint32_t b1) {
    asm volatile(
        "mma.sync.aligned.m16n8k16.row.col.f32.bf16.bf16.f32 "
        "{%0,%1,%2,%3}, {%4,%5,%6,%7}, {%8,%9}, {%0,%1,%2,%3};"
        : "+f"(c[0]), "+f"(c[1]), "+f"(c[2]), "+f"(c[3])
        : "r"(a[0]), "r"(a[1]), "r"(a[2]), "r"(a[3]), "r"(b0), "r"(b1));
}
__device__ __forceinline__ void split1(float v, __nv_bfloat16& h, __nv_bfloat16& l) {
    h = __float2bfloat16(v);
    l = __float2bfloat16(v - __bfloat162float(h));
}
__device__ __forceinline__ void split_store4(float4 v, __nv_bfloat16* dh,
                                             __nv_bfloat16* dl) {
    __nv_bfloat16 h0, h1, h2, h3, l0, l1, l2, l3;
    split1(v.x, h0, l0); split1(v.y, h1, l1);
    split1(v.z, h2, l2); split1(v.w, h3, l3);
    __nv_bfloat162 p;
    p.x = h0; p.y = h1; ((__nv_bfloat162*)dh)[0] = p;
    p.x = h2; p.y = h3; ((__nv_bfloat162*)dh)[1] = p;
    p.x = l0; p.y = l1; ((__nv_bfloat162*)dl)[0] = p;
    p.x = l2; p.y = l3; ((__nv_bfloat162*)dl)[1] = p;
}

// ------------------------- weight split kernel (+ barrier reset) ------------
__global__ void k_cvt(const float* __restrict__ Wiou, const float* __restrict__ Uiou,
                      const float* __restrict__ Wf, const float* __restrict__ Uf)
{
    if (blockIdx.x == 0 && threadIdx.x < 32) g_counts[threadIdx.x] = 0;
    int idx = blockIdx.x * 256 + threadIdx.x;     // 384*128
    int n = idx >> 7, k = idx & 127;
    split1(Wiou[k * D3 + n], g_Wiou_h[n * 128 + k], g_Wiou_l[n * 128 + k]);
    split1(Uiou[k * D3 + n], g_Uiou_h[n * 128 + k], g_Uiou_l[n * 128 + k]);
    if (n < 128) {
        split1(Wf[k * 128 + n], g_Wf_h[n * 128 + k], g_Wf_l[n * 128 + k]);
        split1(Uf[k * 128 + n], g_Uf_h[n * 128 + k], g_Uf_l[n * 128 + k]);
    }
}

// ------------------------- wxiou GEMM, gate-interleaved + leaf fused --------
// Each CTA: 64 rows x 32 within-gate cols, B tile = 96 rows {i,o,u interleaved
// per octet}. Leaf rows finish the LSTM cell; internal rows store wxiou.
#define WX_SMEM ((2 * 64 + 2 * 96) * SA * 2)   // 87,040 B
__global__ __launch_bounds__(128) void k_wxiou(const float* __restrict__ Asrc,
                                               const float* __restrict__ bias,
                                               float* __restrict__ hout)
{
    extern __shared__ __nv_bfloat16 sm[];
    __nv_bfloat16* As_h = sm;
    __nv_bfloat16* As_l = sm + 64 * SA;
    __nv_bfloat16* Bs_h = sm + 128 * SA;
    __nv_bfloat16* Bs_l = sm + (128 + 96) * SA;

    const int tid = threadIdx.x;
    const int row0 = blockIdx.x * 64;
    const int nb = blockIdx.y;     // 0..3: within-gate col block of 32

    // B copy: 96 local rows; lr = o*24 + s*8 + jj  <->  n = nb*32 + o*8 + jj + s*128
    for (int j = tid; j < 96 * 16; j += 128) {
        int lr = j >> 4, q = j & 15;
        int o = lr / 24, rem = lr - o * 24;
        int s = rem >> 3, jj = rem & 7;
        int n = nb * 32 + o * 8 + jj + s * 128;
        *(uint4*)&Bs_h[lr * SA + q * 8] = *(const uint4*)&g_Wiou_h[n * 128 + q * 8];
        *(uint4*)&Bs_l[lr * SA + q * 8] = *(const uint4*)&g_Wiou_l[n * 128 + q * 8];
    }
#pragma unroll
    for (int s = 0; s < 16; s++) {
        int j = tid + s * 128;
        int r = j >> 5, kq = j & 31;
        int L = row0 + r;
        int g = (L < NN) ? L : NN - 1;
        float4 v = *(const float4*)&Asrc[g * 128 + kq * 4];
        split_store4(v, &As_h[r * SA + kq * 4], &As_l[r * SA + kq * 4]);
    }
    __syncthreads();

    const int lane = tid & 31, wid = tid >> 5;
    const int wm = (wid & 1) * 32;
    const int wn = wid >> 1;       // 0..1 : two octets each

    float acc[2][6][4];
#pragma unroll
    for (int i = 0; i < 2; i++)
#pragma unroll
        for (int j = 0; j < 6; j++)
#pragma unroll
            for (int k = 0; k < 4; k++) acc[i][j][k] = 0.0f;

    const uint32_t smbase = (uint32_t)__cvta_generic_to_shared(sm);
    const uint32_t offAl = 64 * SA * 2;
    const uint32_t offBh = 128 * SA * 2;
    const uint32_t offBl = (128 + 96) * SA * 2;

    const int rA = lane & 15;
    const int kA8 = (lane >> 4) * 8;
    uint32_t adA0 = smbase + ((wm + rA) * SA + kA8) * 2;
    uint32_t adA1 = smbase + ((wm + 16 + rA) * SA + kA8) * 2;
    const int rB = (lane & 7) + ((lane >> 4) * 8);
    const int kB8 = ((lane >> 3) & 1) * 8;
    uint32_t adB[3];
#pragma unroll
    for (int i = 0; i < 3; i++)
        adB[i] = smbase + offBh + ((wn * 48 + i * 16 + rB) * SA + kB8) * 2;

#pragma unroll
    for (int kc = 0; kc < 8; kc++) {
        const uint32_t ko = kc * 32;
        uint32_t a_h[2][4], a_l[2][4], b_h[3][4], b_l[3][4];
        ldsm4(adA0 + ko, a_h[0]);
        ldsm4(adA1 + ko, a_h[1]);
        ldsm4(adA0 + offAl + ko, a_l[0]);
        ldsm4(adA1 + offAl + ko, a_l[1]);
#pragma unroll
        for (int i = 0; i < 3; i++) {
            ldsm4(adB[i] + ko, b_h[i]);
            ldsm4(adB[i] + (offBl - offBh) + ko, b_l[i]);
        }
#pragma unroll
        for (int mi = 0; mi < 2; mi++)
#pragma unroll
            for (int nt = 0; nt < 6; nt++) {
                uint32_t bh0 = b_h[nt >> 1][(nt & 1) * 2];
                uint32_t bh1 = b_h[nt >> 1][(nt & 1) * 2 + 1];
                uint32_t bl0 = b_l[nt >> 1][(nt & 1) * 2];
                uint32_t bl1 = b_l[nt >> 1][(nt & 1) * 2 + 1];
                mma16816(acc[mi][nt], a_h[mi], bh0, bh1);
                mma16816(acc[mi][nt], a_l[mi], bh0, bh1);
                mma16816(acc[mi][nt], a_h[mi], bl0, bl1);
            }
    }

    const int er = lane >> 2;
    const int ec = (lane & 3) * 2;
#pragma unroll
    for (int mi = 0; mi < 2; mi++)
#pragma unroll
        for (int ol = 0; ol < 2; ol++) {
            int col = nb * 32 + (2 * wn + ol) * 8 + ec;   // within-gate col
            int a0 = ol * 3;
#pragma unroll
            for (int half = 0; half < 2; half++) {
                int L = row0 + wm + mi * 16 + er + half * 8;
                if (L >= NN) continue;
                int t = L / MT;
                int rr = L - t * MT;
                float i0 = acc[mi][a0 + 0][half * 2 + 0] + bias[col];
                float i1 = acc[mi][a0 + 0][half * 2 + 1] + bias[col + 1];
                float o0 = acc[mi][a0 + 1][half * 2 + 0] + bias[128 + col];
                float o1 = acc[mi][a0 + 1][half * 2 + 1] + bias[128 + col + 1];
                float u0 = acc[mi][a0 + 2][half * 2 + 0] + bias[256 + col];
                float u1 = acc[mi][a0 + 2][half * 2 + 1] + bias[256 + col + 1];
                if (rr >= 1023) {   // leaf: finish cell
                    float2 cv, hv;
                    float cn0 = sigf(i0) * tanhfast(u0);
                    float cn1 = sigf(i1) * tanhfast(u1);
                    cv.x = cn0; cv.y = cn1;
                    hv.x = sigf(o0) * tanhfast(cn0);
                    hv.y = sigf(o1) * tanhfast(cn1);
                    *(float2*)&g_c[L * 128 + col] = cv;
                    *(float2*)&hout[L * 128 + col] = hv;
                } else {
                    float2 a;
                    a.x = i0; a.y = i1;
                    *(float2*)&g_wxiou[L * D3 + col] = a;
                    a.x = o0; a.y = o1;
                    *(float2*)&g_wxiou[L * D3 + 128 + col] = a;
                    a.x = u0; a.y = u1;
                    *(float2*)&g_wxiou[L * D3 + 256 + col] = a;
                }
            }
        }
}

// ------------------------- wxf precompute GEMM (N=128 resident) -------------
#define G128_SMEM ((2 * 64 + 2 * 128) * SA * 2)
__global__ __launch_bounds__(256) void k_wxf(const float* __restrict__ Asrc,
                                             const float* __restrict__ bias)
{
    extern __shared__ __nv_bfloat16 sm[];
    __nv_bfloat16* As_h = sm;
    __nv_bfloat16* As_l = sm + 64 * SA;
    __nv_bfloat16* Bs_h = sm + 2 * 64 * SA;
    __nv_bfloat16* Bs_l = sm + (2 * 64 + 128) * SA;

    const int tid = threadIdx.x;
    const int L0 = blockIdx.x * 64;

#pragma unroll
    for (int s = 0; s < 8; s++) {
        int j = tid + s * 256;
        int r = j >> 4, q = j & 15;
        *(uint4*)&Bs_h[r * SA + q * 8] = *(const uint4*)&g_Wf_h[r * 128 + q * 8];
        *(uint4*)&Bs_l[r * SA + q * 8] = *(const uint4*)&g_Wf_l[r * 128 + q * 8];
    }
#pragma unroll
    for (int s = 0; s < 8; s++) {
        int j = tid + s * 256;
        int r = j >> 5, kq = j & 31;
        int L = L0 + r;
        int Lc = (L < NINT) ? L : NINT - 1;
        int t = Lc / 1023;
        int g = t * MT + (Lc - t * 1023);
        float4 v = *(const float4*)&Asrc[g * 128 + kq * 4];
        split_store4(v, &As_h[r * SA + kq * 4], &As_l[r * SA + kq * 4]);
    }
    __syncthreads();

    const int lane = tid & 31, wid = tid >> 5;
    const int wm = (wid & 1) * 32, wn = (wid >> 1) * 32;

    float acc[2][4][4];
#pragma unroll
    for (int i = 0; i < 2; i++)
#pragma unroll
        for (int j = 0; j < 4; j++)
#pragma unroll
            for (int k = 0; k < 4; k++) acc[i][j][k] = 0.0f;

    const uint32_t smbase = (uint32_t)__cvta_generic_to_shared(sm);
    const uint32_t offAl = 64 * SA * 2;
    const uint32_t offBh = 2 * 64 * SA * 2;
    const uint32_t offBl = (2 * 64 + 128) * SA * 2;

    const int rA = lane & 15;
    const int kA8 = (lane >> 4) * 8;
    uint32_t adA0 = smbase + ((wm + rA) * SA + kA8) * 2;
    uint32_t adA1 = smbase + ((wm + 16 + rA) * SA + kA8) * 2;
    const int rB = (lane & 7) + ((lane >> 4) * 8);
    const int kB8 = ((lane >> 3) & 1) * 8;
    uint32_t adB0 = smbase + offBh + ((wn + rB) * SA + kB8) * 2;
    uint32_t adB1 = smbase + offBh + ((wn + 16 + rB) * SA + kB8) * 2;

#pragma unroll
    for (int kc = 0; kc < 8; kc++) {
        const uint32_t ko = kc * 32;
        uint32_t a_h[2][4], a_l[2][4], b_h[2][4], b_l[2][4];
        ldsm4(adA0 + ko, a_h[0]);
        ldsm4(adA1 + ko, a_h[1]);
        ldsm4(adA0 + offAl + ko, a_l[0]);
        ldsm4(adA1 + offAl + ko, a_l[1]);
        ldsm4(adB0 + ko, b_h[0]);
        ldsm4(adB1 + ko, b_h[1]);
        ldsm4(adB0 + (offBl - offBh) + ko, b_l[0]);
        ldsm4(adB1 + (offBl - offBh) + ko, b_l[1]);
#pragma unroll
        for (int mi = 0; mi < 2; mi++)
#pragma unroll
            for (int nt = 0; nt < 4; nt++) {
                uint32_t bh0 = b_h[nt >> 1][(nt & 1) * 2];
                uint32_t bh1 = b_h[nt >> 1][(nt & 1) * 2 + 1];
                uint32_t bl0 = b_l[nt >> 1][(nt & 1) * 2];
                uint32_t bl1 = b_l[nt >> 1][(nt & 1) * 2 + 1];
                mma16816(acc[mi][nt], a_h[mi], bh0, bh1);
                mma16816(acc[mi][nt], a_l[mi], bh0, bh1);
                mma16816(acc[mi][nt], a_h[mi], bl0, bl1);
            }
    }

    const int er = lane >> 2;
    const int ec = (lane & 3) * 2;
#pragma unroll
    for (int mi = 0; mi < 2; mi++)
#pragma unroll
        for (int nt = 0; nt < 4; nt++) {
            int n = wn + nt * 8 + ec;
#pragma unroll
            for (int half = 0; half < 2; half++) {
                int L = L0 + wm + mi * 16 + er + half * 8;
                if (L < NINT) {
                    int t = L / 1023;
                    int g = t * MT + (L - t * 1023);
                    float2 o;
                    o.x = acc[mi][nt][half * 2 + 0] + bias[n];
                    o.y = acc[mi][nt][half * 2 + 1] + bias[n + 1];
                    *(float2*)&g_wxf[g * 128 + n] = o;
                }
            }
        }
}

// ------------------------- persistent merged level kernel -------------------
// Per level dd, per unit (64 children + their 32 parents, one CTA):
//   build As(child h) + Ap(pairsum) -> F (Uf in 2x64-col chunks) -> fc to g_fc
//   -> IOU (Uiou in 6x64-col chunks, accs retained) -> full cell update.
// Barrier only between levels (9 total).
#define LV_SMEM ((2 * 64 + 2 * 32 + 2 * 64) * SA * 2)   // 87,040 B

__device__ __forceinline__ void gbar(int slot, int G) {
    __syncthreads();
    if (threadIdx.x == 0) {
        __threadfence();
        atomicAdd(&g_counts[slot], 1u);
        while (atomicAdd(&g_counts[slot], 0u) < (unsigned)G) __nanosleep(64);
        __threadfence();
    }
    __syncthreads();
}

__global__ __launch_bounds__(256, 2) void k_levels(float* __restrict__ h, int G)
{
    extern __shared__ __nv_bfloat16 sm[];
    const int tid = threadIdx.x, lane = tid & 31, wid = tid >> 5;
    const int bid = blockIdx.x;

    __nv_bfloat16* As_h = sm;                  // 64 rows
    __nv_bfloat16* As_l = sm + 64 * SA;
    __nv_bfloat16* Ap_h = sm + 128 * SA;       // 32 rows
    __nv_bfloat16* Ap_l = sm + 160 * SA;
    __nv_bfloat16* Bs_h = sm + 192 * SA;       // 64 rows
    __nv_bfloat16* Bs_l = sm + 256 * SA;

    const uint32_t smbase = (uint32_t)__cvta_generic_to_shared(sm);
    const uint32_t oAsl = 64 * SA * 2;
    const uint32_t oAp  = 128 * SA * 2;
    const uint32_t oApl = 160 * SA * 2;
    const uint32_t oB   = 192 * SA * 2;
    const uint32_t oBl  = 256 * SA * 2;

    const int rA = lane & 15;
    const int kA8 = (lane >> 4) * 8;
    const int rB = (lane & 7) + ((lane >> 4) * 8);
    const int kB8 = ((lane >> 3) & 1) * 8;
    const int er = lane >> 2;
    const int ec = (lane & 3) * 2;

    // F tiling: 4m x 2n (m16, n32); IOU tiling: 2m x 4n (m16, n16)
    const int fwm = (wid & 3) * 16, fwn = wid >> 2;
    const int iwm = (wid & 1) * 16, iwn = wid >> 1;

    int slot = 0;
    for (int dd = 9; dd >= 0; dd--) {
        const int cs = dd + 1;
        const int CH = 1 << cs;
        const int P = 1 << dd;
        const int nU = 1 << dd;

        for (int u = bid; u < nU; u += G) {
            __syncthreads();
            // ---- build As (64 child rows) + Ap (32 pairsum rows) ----
#pragma unroll
            for (int s = 0; s < 8; s++) {
                int j = tid + s * 256;
                int r = j >> 5, kq = j & 31;
                int L = u * 64 + r;
                int t = L >> cs, rr = L & (CH - 1);
                int gc = t * MT + (CH - 1) + rr;
                float4 v = *(const float4*)&h[gc * 128 + kq * 4];
                split_store4(v, &As_h[r * SA + kq * 4], &As_l[r * SA + kq * 4]);
            }
#pragma unroll
            for (int s = 0; s < 4; s++) {
                int j = tid + s * 256;
                int r = j >> 5, kq = j & 31;
                int Lp = u * 32 + r;
                int t = Lp >> dd, rr = Lp & (P - 1);
                int gc1 = t * MT + 2 * P - 1 + 2 * rr;
                float4 v1 = *(const float4*)&h[gc1 * 128 + kq * 4];
                float4 v2 = *(const float4*)&h[(gc1 + 1) * 128 + kq * 4];
                float4 v = make_float4(v1.x + v2.x, v1.y + v2.y,
                                       v1.z + v2.z, v1.w + v2.w);
                split_store4(v, &Ap_h[r * SA + kq * 4], &Ap_l[r * SA + kq * 4]);
            }

            // ---- F: 2 chunks of 64 cols ----
            {
                uint32_t adA0 = smbase + ((fwm + rA) * SA + kA8) * 2;
                uint32_t adB0 = smbase + oB + ((fwn * 32 + rB) * SA + kB8) * 2;
                uint32_t adB1 = smbase + oB + ((fwn * 32 + 16 + rB) * SA + kB8) * 2;
#pragma unroll
                for (int q = 0; q < 2; q++) {
                    __syncthreads();
#pragma unroll
                    for (int s = 0; s < 4; s++) {
                        int j = tid + s * 256;
                        int r = j >> 4, qq = j & 15;
                        *(uint4*)&Bs_h[r * SA + qq * 8] =
                            *(const uint4*)&g_Uf_h[(q * 64 + r) * 128 + qq * 8];
                        *(uint4*)&Bs_l[r * SA + qq * 8] =
                            *(const uint4*)&g_Uf_l[(q * 64 + r) * 128 + qq * 8];
                    }
                    __syncthreads();

                    float facc[4][4];
#pragma unroll
                    for (int j = 0; j < 4; j++)
#pragma unroll
                        for (int k = 0; k < 4; k++) facc[j][k] = 0.0f;
#pragma unroll
                    for (int kc = 0; kc < 8; kc++) {
                        const uint32_t ko = kc * 32;
                        uint32_t a_h[4], a_l[4], b_h[2][4], b_l[2][4];
                        ldsm4(adA0 + ko, a_h);
                        ldsm4(adA0 + oAsl + ko, a_l);
                        ldsm4(adB0 + ko, b_h[0]);
                        ldsm4(adB1 + ko, b_h[1]);
                        ldsm4(adB0 + (oBl - oB) + ko, b_l[0]);
                        ldsm4(adB1 + (oBl - oB) + ko, b_l[1]);
#pragma unroll
                        for (int nt = 0; nt < 4; nt++) {
                            uint32_t bh0 = b_h[nt >> 1][(nt & 1) * 2];
                            uint32_t bh1 = b_h[nt >> 1][(nt & 1) * 2 + 1];
                            uint32_t bl0 = b_l[nt >> 1][(nt & 1) * 2];
                            uint32_t bl1 = b_l[nt >> 1][(nt & 1) * 2 + 1];
                            mma16816(facc[nt], a_h, bh0, bh1);
                            mma16816(facc[nt], a_l, bh0, bh1);
                            mma16816(facc[nt], a_h, bl0, bl1);
                        }
                    }
                    // fc epilogue
#pragma unroll
                    for (int nt = 0; nt < 4; nt++) {
                        int n = q * 64 + fwn * 32 + nt * 8 + ec;
#pragma unroll
                        for (int half = 0; half < 2; half++) {
                            int lr = fwm + er + half * 8;
                            int L = u * 64 + lr;
                            int t = L >> cs, rr = L & (CH - 1);
                            int gc = t * MT + (CH - 1) + rr;
                            int gp = t * MT + ((CH >> 1) - 1) + (rr >> 1);
                            float2 wf = *(const float2*)&g_wxf[gp * 128 + n];
                            float2 cc = *(const float2*)&g_c[gc * 128 + n];
                            float2 o;
                            o.x = sigf(facc[nt][half * 2 + 0] + wf.x) * cc.x;
                            o.y = sigf(facc[nt][half * 2 + 1] + wf.y) * cc.y;
                            *(float2*)&g_fc[gc * 128 + n] = o;
                        }
                    }
                }
            }

            // ---- IOU: 6 chunks of 64 cols, accs retained ----
            float iacc[6][2][4];
#pragma unroll
            for (int c = 0; c < 6; c++)
#pragma unroll
                for (int j = 0; j < 2; j++)
#pragma unroll
                    for (int k = 0; k < 4; k++) iacc[c][j][k] = 0.0f;
            {
                uint32_t adA = smbase + oAp + ((iwm + rA) * SA + kA8) * 2;
                uint32_t adB = smbase + oB + ((iwn * 16 + rB) * SA + kB8) * 2;
#pragma unroll
                for (int ch = 0; ch < 6; ch++) {
                    __syncthreads();
#pragma unroll
                    for (int s = 0; s < 4; s++) {
                        int j = tid + s * 256;
                        int r = j >> 4, qq = j & 15;
                        *(uint4*)&Bs_h[r * SA + qq * 8] =
                            *(const uint4*)&g_Uiou_h[(ch * 64 + r) * 128 + qq * 8];
                        *(uint4*)&Bs_l[r * SA + qq * 8] =
                            *(const uint4*)&g_Uiou_l[(ch * 64 + r) * 128 + qq * 8];
                    }
                    __syncthreads();
#pragma unroll
                    for (int kc = 0; kc < 8; kc++) {
                        const uint32_t ko = kc * 32;
                        uint32_t a_h[4], a_l[4], b_h[4], b_l[4];
                        ldsm4(adA + ko, a_h);
                        ldsm4(adA + (oApl - oAp) + ko, a_l);
                        ldsm4(adB + ko, b_h);
                        ldsm4(adB + (oBl - oB) + ko, b_l);
#pragma unroll
                        for (int nt = 0; nt < 2; nt++) {
                            uint32_t bh0 = b_h[nt * 2], bh1 = b_h[nt * 2 + 1];
                            uint32_t bl0 = b_l[nt * 2], bl1 = b_l[nt * 2 + 1];
                            mma16816(iacc[ch][nt], a_h, bh0, bh1);
                            mma16816(iacc[ch][nt], a_l, bh0, bh1);
                            mma16816(iacc[ch][nt], a_h, bl0, bl1);
                        }
                    }
                }
            }
            // ---- cell epilogue ----
#pragma unroll
            for (int qb = 0; qb < 2; qb++)
#pragma unroll
                for (int nt = 0; nt < 2; nt++) {
                    int col = qb * 64 + iwn * 16 + nt * 8 + ec;  // 0..127
#pragma unroll
                    for (int half = 0; half < 2; half++) {
                        int pr = iwm + er + half * 8;
                        int Lp = u * 32 + pr;
                        int t = Lp >> dd, rr = Lp & (P - 1);
                        int gp = t * MT + P - 1 + rr;
                        int gc1 = t * MT + 2 * P - 1 + 2 * rr;
                        float2 wi = *(const float2*)&g_wxiou[gp * D3 + col];
                        float2 wo = *(const float2*)&g_wxiou[gp * D3 + 128 + col];
                        float2 wu = *(const float2*)&g_wxiou[gp * D3 + 256 + col];
                        float2 f1 = *(const float2*)&g_fc[gc1 * 128 + col];
                        float2 f2 = *(const float2*)&g_fc[(gc1 + 1) * 128 + col];
                        float i0 = iacc[0 + qb][nt][half * 2 + 0] + wi.x;
                        float i1 = iacc[0 + qb][nt][half * 2 + 1] + wi.y;
                        float o0 = iacc[2 + qb][nt][half * 2 + 0] + wo.x;
                        float o1 = iacc[2 + qb][nt][half * 2 + 1] + wo.y;
                        float u0 = iacc[4 + qb][nt][half * 2 + 0] + wu.x;
                        float u1 = iacc[4 + qb][nt][half * 2 + 1] + wu.y;
                        float2 cres, hres;
                        float cn0 = sigf(i0) * tanhfast(u0) + f1.x + f2.x;
                        float cn1 = sigf(i1) * tanhfast(u1) + f1.y + f2.y;
                        cres.x = cn0; cres.y = cn1;
                        hres.x = sigf(o0) * tanhfast(cn0);
                        hres.y = sigf(o1) * tanhfast(cn1);
                        *(float2*)&g_c[gp * 128 + col] = cres;
                        *(float2*)&h[gp * 128 + col] = hres;
                    }
                }
        }
        if (dd > 0) gbar(slot++, G);
    }
}

// ---------------------------------------------------------------------------
extern "C" void kernel_launch(void* const* d_in, const int* in_sizes, int n_in,
                              void* d_out, int out_size)
{
    const float* features = (const float*)d_in[0];
    const float* W_iou    = (const float*)d_in[1];
    const float* b_iou    = (const float*)d_in[2];
    const float* U_iou    = (const float*)d_in[3];
    const float* W_f      = (const float*)d_in[4];
    const float* b_f      = (const float*)d_in[5];
    const float* U_f      = (const float*)d_in[6];
    float* h = (float*)d_out;

    (void)cudaFuncSetAttribute(k_wxiou, cudaFuncAttributeMaxDynamicSharedMemorySize, WX_SMEM);
    (void)cudaFuncSetAttribute(k_wxf, cudaFuncAttributeMaxDynamicSharedMemorySize, G128_SMEM);
    (void)cudaFuncSetAttribute(k_levels, cudaFuncAttributeMaxDynamicSharedMemorySize, LV_SMEM);

    int nsm = 148, occ = 1;
    (void)cudaDeviceGetAttribute(&nsm, cudaDevAttrMultiProcessorCount, 0);
    (void)cudaOccupancyMaxActiveBlocksPerMultiprocessor(&occ, k_levels, 256, LV_SMEM);
    if (occ < 1) occ = 1;
    if (occ > 2) occ = 2;
    int G = nsm * occ;

    k_cvt<<<192, 256>>>(W_iou, U_iou, W_f, U_f);   // also resets g_counts
    k_wxiou<<<dim3(1024, 4), 128, WX_SMEM>>>(features, b_iou, h);
    k_wxf<<<512, 256, G128_SMEM>>>(features, b_f);
    k_levels<<<G, 256, LV_SMEM>>>(h, G);
}

// round 11
// speedup vs baseline: 1.3862x; 1.3862x over previous
#include <cuda_runtime.h>
#include <cuda_bf16.h>
#include <cstdint>

#define D3 384
#define MT 2047          // nodes per tree
#define NT 32
#define NN 65504         // 32 * 2047
#define NINT 32736       // 32 * 1023 internal nodes
#define SA 136           // smem row stride in bf16 (272B) -> ldmatrix conflict-free

// ------------------------- device scratch ----------------------------------
__device__ float g_wxiou[NN * D3];      // W_iou*x + b_iou (internal nodes only)
__device__ float g_wxf[NN * 128];       // W_f*x + b_f, internal nodes
__device__ float g_c[NN * 128];         // cell state
__device__ float g_fc[NN * 128];        // f(child)*c(child)
__device__ unsigned g_counts[32];       // global barrier slots (reset by k_cvt)

__device__ __align__(16) __nv_bfloat16 g_Wiou_h[D3 * 128];
__device__ __align__(16) __nv_bfloat16 g_Wiou_l[D3 * 128];
__device__ __align__(16) __nv_bfloat16 g_Uiou_h[D3 * 128];
__device__ __align__(16) __nv_bfloat16 g_Uiou_l[D3 * 128];
__device__ __align__(16) __nv_bfloat16 g_Wf_h[128 * 128];
__device__ __align__(16) __nv_bfloat16 g_Wf_l[128 * 128];
__device__ __align__(16) __nv_bfloat16 g_Uf_h[128 * 128];
__device__ __align__(16) __nv_bfloat16 g_Uf_l[128 * 128];

__device__ __forceinline__ float sigf(float x) {
    return 1.0f / (1.0f + __expf(-x));
}
__device__ __forceinline__ float tanhfast(float x) {
    return 1.0f - 2.0f / (__expf(2.0f * x) + 1.0f);
}

// ------------------------- mma / ldmatrix helpers ---------------------------
__device__ __forceinline__ void ldsm4(uint32_t addr, uint32_t* r) {
    asm volatile("ldmatrix.sync.aligned.m8n8.x4.shared.b16 {%0,%1,%2,%3}, [%4];"
                 : "=r"(r[0]), "=r"(r[1]), "=r"(r[2]), "=r"(r[3]) : "r"(addr));
}
__device__ __forceinline__ void ldsm2(uint32_t addr, uint32_t* r) {
    asm volatile("ldmatrix.sync.aligned.m8n8.x2.shared.b16 {%0,%1}, [%2];"
                 : "=r"(r[0]), "=r"(r[1]) : "r"(addr));
}
__device__ __forceinline__ void mma16816(float* c, const uint32_t* a,
                                         uint32_t b0, uint32_t b1) {
    asm volatile(
        "mma.sync.aligned.m16n8k16.row.col.f32.bf16.bf16.f32 "
        "{%0,%1,%2,%3}, {%4,%5,%6,%7}, {%8,%9}, {%0,%1,%2,%3};"
        : "+f"(c[0]), "+f"(c[1]), "+f"(c[2]), "+f"(c[3])
        : "r"(a[0]), "r"(a[1]), "r"(a[2]), "r"(a[3]), "r"(b0), "r"(b1));
}
__device__ __forceinline__ void split1(float v, __nv_bfloat16& h, __nv_bfloat16& l) {
    h = __float2bfloat16(v);
    l = __float2bfloat16(v - __bfloat162float(h));
}
__device__ __forceinline__ void split_store4(float4 v, __nv_bfloat16* dh,
                                             __nv_bfloat16* dl) {
    __nv_bfloat16 h0, h1, h2, h3, l0, l1, l2, l3;
    split1(v.x, h0, l0); split1(v.y, h1, l1);
    split1(v.z, h2, l2); split1(v.w, h3, l3);
    __nv_bfloat162 p;
    p.x = h0; p.y = h1; ((__nv_bfloat162*)dh)[0] = p;
    p.x = h2; p.y = h3; ((__nv_bfloat162*)dh)[1] = p;
    p.x = l0; p.y = l1; ((__nv_bfloat162*)dl)[0] = p;
    p.x = l2; p.y = l3; ((__nv_bfloat162*)dl)[1] = p;
}

// ------------------------- weight split kernel (+ barrier reset) ------------
__global__ void k_cvt(const float* __restrict__ Wiou, const float* __restrict__ Uiou,
                      const float* __restrict__ Wf, const float* __restrict__ Uf)
{
    if (blockIdx.x == 0 && threadIdx.x < 32) g_counts[threadIdx.x] = 0;
    int idx = blockIdx.x * 256 + threadIdx.x;     // 384*128
    int n = idx >> 7, k = idx & 127;
    split1(Wiou[k * D3 + n], g_Wiou_h[n * 128 + k], g_Wiou_l[n * 128 + k]);
    split1(Uiou[k * D3 + n], g_Uiou_h[n * 128 + k], g_Uiou_l[n * 128 + k]);
    if (n < 128) {
        split1(Wf[k * 128 + n], g_Wf_h[n * 128 + k], g_Wf_l[n * 128 + k]);
        split1(Uf[k * 128 + n], g_Uf_h[n * 128 + k], g_Uf_l[n * 128 + k]);
    }
}

// ------------------------- wxiou GEMM, gate-interleaved + leaf fused --------
#define WX_SMEM ((2 * 64 + 2 * 96) * SA * 2)   // 87,040 B
__global__ __launch_bounds__(128) void k_wxiou(const float* __restrict__ Asrc,
                                               const float* __restrict__ bias,
                                               float* __restrict__ hout)
{
    extern __shared__ __nv_bfloat16 sm[];
    __nv_bfloat16* As_h = sm;
    __nv_bfloat16* As_l = sm + 64 * SA;
    __nv_bfloat16* Bs_h = sm + 128 * SA;
    __nv_bfloat16* Bs_l = sm + (128 + 96) * SA;

    const int tid = threadIdx.x;
    const int row0 = blockIdx.x * 64;
    const int nb = blockIdx.y;     // 0..3: within-gate col block of 32

    for (int j = tid; j < 96 * 16; j += 128) {
        int lr = j >> 4, q = j & 15;
        int o = lr / 24, rem = lr - o * 24;
        int s = rem >> 3, jj = rem & 7;
        int n = nb * 32 + o * 8 + jj + s * 128;
        *(uint4*)&Bs_h[lr * SA + q * 8] = *(const uint4*)&g_Wiou_h[n * 128 + q * 8];
        *(uint4*)&Bs_l[lr * SA + q * 8] = *(const uint4*)&g_Wiou_l[n * 128 + q * 8];
    }
#pragma unroll
    for (int s = 0; s < 16; s++) {
        int j = tid + s * 128;
        int r = j >> 5, kq = j & 31;
        int L = row0 + r;
        int g = (L < NN) ? L : NN - 1;
        float4 v = *(const float4*)&Asrc[g * 128 + kq * 4];
        split_store4(v, &As_h[r * SA + kq * 4], &As_l[r * SA + kq * 4]);
    }
    __syncthreads();

    const int lane = tid & 31, wid = tid >> 5;
    const int wm = (wid & 1) * 32;
    const int wn = wid >> 1;       // 0..1 : two octets each

    float acc[2][6][4];
#pragma unroll
    for (int i = 0; i < 2; i++)
#pragma unroll
        for (int j = 0; j < 6; j++)
#pragma unroll
            for (int k = 0; k < 4; k++) acc[i][j][k] = 0.0f;

    const uint32_t smbase = (uint32_t)__cvta_generic_to_shared(sm);
    const uint32_t offAl = 64 * SA * 2;
    const uint32_t offBh = 128 * SA * 2;
    const uint32_t offBl = (128 + 96) * SA * 2;

    const int rA = lane & 15;
    const int kA8 = (lane >> 4) * 8;
    uint32_t adA0 = smbase + ((wm + rA) * SA + kA8) * 2;
    uint32_t adA1 = smbase + ((wm + 16 + rA) * SA + kA8) * 2;
    const int rB = (lane & 7) + ((lane >> 4) * 8);
    const int kB8 = ((lane >> 3) & 1) * 8;
    uint32_t adB[3];
#pragma unroll
    for (int i = 0; i < 3; i++)
        adB[i] = smbase + offBh + ((wn * 48 + i * 16 + rB) * SA + kB8) * 2;

#pragma unroll
    for (int kc = 0; kc < 8; kc++) {
        const uint32_t ko = kc * 32;
        uint32_t a_h[2][4], a_l[2][4], b_h[3][4], b_l[3][4];
        ldsm4(adA0 + ko, a_h[0]);
        ldsm4(adA1 + ko, a_h[1]);
        ldsm4(adA0 + offAl + ko, a_l[0]);
        ldsm4(adA1 + offAl + ko, a_l[1]);
#pragma unroll
        for (int i = 0; i < 3; i++) {
            ldsm4(adB[i] + ko, b_h[i]);
            ldsm4(adB[i] + (offBl - offBh) + ko, b_l[i]);
        }
#pragma unroll
        for (int mi = 0; mi < 2; mi++)
#pragma unroll
            for (int nt = 0; nt < 6; nt++) {
                uint32_t bh0 = b_h[nt >> 1][(nt & 1) * 2];
                uint32_t bh1 = b_h[nt >> 1][(nt & 1) * 2 + 1];
                uint32_t bl0 = b_l[nt >> 1][(nt & 1) * 2];
                uint32_t bl1 = b_l[nt >> 1][(nt & 1) * 2 + 1];
                mma16816(acc[mi][nt], a_h[mi], bh0, bh1);
                mma16816(acc[mi][nt], a_l[mi], bh0, bh1);
                mma16816(acc[mi][nt], a_h[mi], bl0, bl1);
            }
    }

    const int er = lane >> 2;
    const int ec = (lane & 3) * 2;
#pragma unroll
    for (int mi = 0; mi < 2; mi++)
#pragma unroll
        for (int ol = 0; ol < 2; ol++) {
            int col = nb * 32 + (2 * wn + ol) * 8 + ec;
            int a0 = ol * 3;
#pragma unroll
            for (int half = 0; half < 2; half++) {
                int L = row0 + wm + mi * 16 + er + half * 8;
                if (L >= NN) continue;
                int t = L / MT;
                int rr = L - t * MT;
                float i0 = acc[mi][a0 + 0][half * 2 + 0] + bias[col];
                float i1 = acc[mi][a0 + 0][half * 2 + 1] + bias[col + 1];
                float o0 = acc[mi][a0 + 1][half * 2 + 0] + bias[128 + col];
                float o1 = acc[mi][a0 + 1][half * 2 + 1] + bias[128 + col + 1];
                float u0 = acc[mi][a0 + 2][half * 2 + 0] + bias[256 + col];
                float u1 = acc[mi][a0 + 2][half * 2 + 1] + bias[256 + col + 1];
                if (rr >= 1023) {
                    float2 cv, hv;
                    float cn0 = sigf(i0) * tanhfast(u0);
                    float cn1 = sigf(i1) * tanhfast(u1);
                    cv.x = cn0; cv.y = cn1;
                    hv.x = sigf(o0) * tanhfast(cn0);
                    hv.y = sigf(o1) * tanhfast(cn1);
                    *(float2*)&g_c[L * 128 + col] = cv;
                    *(float2*)&hout[L * 128 + col] = hv;
                } else {
                    float2 a;
                    a.x = i0; a.y = i1;
                    *(float2*)&g_wxiou[L * D3 + col] = a;
                    a.x = o0; a.y = o1;
                    *(float2*)&g_wxiou[L * D3 + 128 + col] = a;
                    a.x = u0; a.y = u1;
                    *(float2*)&g_wxiou[L * D3 + 256 + col] = a;
                }
            }
        }
}

// ------------------------- wxf precompute GEMM (N=128 resident) -------------
#define G128_SMEM ((2 * 64 + 2 * 128) * SA * 2)
__global__ __launch_bounds__(256) void k_wxf(const float* __restrict__ Asrc,
                                             const float* __restrict__ bias)
{
    extern __shared__ __nv_bfloat16 sm[];
    __nv_bfloat16* As_h = sm;
    __nv_bfloat16* As_l = sm + 64 * SA;
    __nv_bfloat16* Bs_h = sm + 2 * 64 * SA;
    __nv_bfloat16* Bs_l = sm + (2 * 64 + 128) * SA;

    const int tid = threadIdx.x;
    const int L0 = blockIdx.x * 64;

#pragma unroll
    for (int s = 0; s < 8; s++) {
        int j = tid + s * 256;
        int r = j >> 4, q = j & 15;
        *(uint4*)&Bs_h[r * SA + q * 8] = *(const uint4*)&g_Wf_h[r * 128 + q * 8];
        *(uint4*)&Bs_l[r * SA + q * 8] = *(const uint4*)&g_Wf_l[r * 128 + q * 8];
    }
#pragma unroll
    for (int s = 0; s < 8; s++) {
        int j = tid + s * 256;
        int r = j >> 5, kq = j & 31;
        int L = L0 + r;
        int Lc = (L < NINT) ? L : NINT - 1;
        int t = Lc / 1023;
        int g = t * MT + (Lc - t * 1023);
        float4 v = *(const float4*)&Asrc[g * 128 + kq * 4];
        split_store4(v, &As_h[r * SA + kq * 4], &As_l[r * SA + kq * 4]);
    }
    __syncthreads();

    const int lane = tid & 31, wid = tid >> 5;
    const int wm = (wid & 1) * 32, wn = (wid >> 1) * 32;

    float acc[2][4][4];
#pragma unroll
    for (int i = 0; i < 2; i++)
#pragma unroll
        for (int j = 0; j < 4; j++)
#pragma unroll
            for (int k = 0; k < 4; k++) acc[i][j][k] = 0.0f;

    const uint32_t smbase = (uint32_t)__cvta_generic_to_shared(sm);
    const uint32_t offAl = 64 * SA * 2;
    const uint32_t offBh = 2 * 64 * SA * 2;
    const uint32_t offBl = (2 * 64 + 128) * SA * 2;

    const int rA = lane & 15;
    const int kA8 = (lane >> 4) * 8;
    uint32_t adA0 = smbase + ((wm + rA) * SA + kA8) * 2;
    uint32_t adA1 = smbase + ((wm + 16 + rA) * SA + kA8) * 2;
    const int rB = (lane & 7) + ((lane >> 4) * 8);
    const int kB8 = ((lane >> 3) & 1) * 8;
    uint32_t adB0 = smbase + offBh + ((wn + rB) * SA + kB8) * 2;
    uint32_t adB1 = smbase + offBh + ((wn + 16 + rB) * SA + kB8) * 2;

#pragma unroll
    for (int kc = 0; kc < 8; kc++) {
        const uint32_t ko = kc * 32;
        uint32_t a_h[2][4], a_l[2][4], b_h[2][4], b_l[2][4];
        ldsm4(adA0 + ko, a_h[0]);
        ldsm4(adA1 + ko, a_h[1]);
        ldsm4(adA0 + offAl + ko, a_l[0]);
        ldsm4(adA1 + offAl + ko, a_l[1]);
        ldsm4(adB0 + ko, b_h[0]);
        ldsm4(adB1 + ko, b_h[1]);
        ldsm4(adB0 + (offBl - offBh) + ko, b_l[0]);
        ldsm4(adB1 + (offBl - offBh) + ko, b_l[1]);
#pragma unroll
        for (int mi = 0; mi < 2; mi++)
#pragma unroll
            for (int nt = 0; nt < 4; nt++) {
                uint32_t bh0 = b_h[nt >> 1][(nt & 1) * 2];
                uint32_t bh1 = b_h[nt >> 1][(nt & 1) * 2 + 1];
                uint32_t bl0 = b_l[nt >> 1][(nt & 1) * 2];
                uint32_t bl1 = b_l[nt >> 1][(nt & 1) * 2 + 1];
                mma16816(acc[mi][nt], a_h[mi], bh0, bh1);
                mma16816(acc[mi][nt], a_l[mi], bh0, bh1);
                mma16816(acc[mi][nt], a_h[mi], bl0, bl1);
            }
    }

    const int er = lane >> 2;
    const int ec = (lane & 3) * 2;
#pragma unroll
    for (int mi = 0; mi < 2; mi++)
#pragma unroll
        for (int nt = 0; nt < 4; nt++) {
            int n = wn + nt * 8 + ec;
#pragma unroll
            for (int half = 0; half < 2; half++) {
                int L = L0 + wm + mi * 16 + er + half * 8;
                if (L < NINT) {
                    int t = L / 1023;
                    int g = t * MT + (L - t * 1023);
                    float2 o;
                    o.x = acc[mi][nt][half * 2 + 0] + bias[n];
                    o.y = acc[mi][nt][half * 2 + 1] + bias[n + 1];
                    *(float2*)&g_wxf[g * 128 + n] = o;
                }
            }
        }
}

// ------------------------- persistent level kernel (resident B) -------------
// Each CTA keeps resident: Uf col-half (bid&1, 64 cols) + Uiou gate-interleaved
// col-group (bid&3: 32 within-gate cols -> 96 rows). Per level:
//   F phase: items = 32-child row units x 2 colhalves -> g_fc;  gbar
//   IOU phase: items = 32-parent row units x 4 colgroups -> full cell; gbar
#define LV_SMEM (384 * SA * 2)   // As(2*32) + Uf(2*64) + Ui(2*96) = 104,448 B

__device__ __forceinline__ void gbar(int slot, int G) {
    __threadfence();
    __syncthreads();
    if (threadIdx.x == 0) {
        atomicAdd(&g_counts[slot], 1u);
        while (atomicAdd(&g_counts[slot], 0u) < (unsigned)G) __nanosleep(64);
    }
    __syncthreads();
}

__global__ __launch_bounds__(256, 2) void k_levels(float* __restrict__ h, int G)
{
    extern __shared__ __nv_bfloat16 sm[];
    const int tid = threadIdx.x, lane = tid & 31, wid = tid >> 5;
    const int bid = blockIdx.x;
    const int colhalf = bid & 1;
    const int colgrp = bid & 3;

    __nv_bfloat16* As_h = sm;                 // 32 rows
    __nv_bfloat16* As_l = sm + 32 * SA;
    __nv_bfloat16* Uf_hS = sm + 64 * SA;      // 64 rows
    __nv_bfloat16* Uf_lS = sm + 128 * SA;
    __nv_bfloat16* Ui_hS = sm + 192 * SA;     // 96 rows
    __nv_bfloat16* Ui_lS = sm + 288 * SA;

    // ---- resident B loads (once per kernel) ----
    for (int j = tid; j < 64 * 16; j += 256) {
        int r = j >> 4, q = j & 15;
        int n = colhalf * 64 + r;
        *(uint4*)&Uf_hS[r * SA + q * 8] = *(const uint4*)&g_Uf_h[n * 128 + q * 8];
        *(uint4*)&Uf_lS[r * SA + q * 8] = *(const uint4*)&g_Uf_l[n * 128 + q * 8];
    }
    for (int j = tid; j < 96 * 16; j += 256) {
        int lr = j >> 4, q = j & 15;
        int wn = lr / 24, rem = lr - wn * 24;
        int gate = rem >> 3, jj = rem & 7;
        int n = gate * 128 + colgrp * 32 + wn * 8 + jj;
        *(uint4*)&Ui_hS[lr * SA + q * 8] = *(const uint4*)&g_Uiou_h[n * 128 + q * 8];
        *(uint4*)&Ui_lS[lr * SA + q * 8] = *(const uint4*)&g_Uiou_l[n * 128 + q * 8];
    }
    __syncthreads();

    const uint32_t smbase = (uint32_t)__cvta_generic_to_shared(sm);
    const uint32_t oAsl = 32 * SA * 2;
    const uint32_t oUf = 64 * SA * 2;
    const uint32_t oUfD = 64 * SA * 2;    // Uf_l - Uf_h
    const uint32_t oUi = 192 * SA * 2;
    const uint32_t oUiD = 96 * SA * 2;    // Ui_l - Ui_h

    const int rA = lane & 15;
    const int kA8 = (lane >> 4) * 8;
    const int rB = (lane & 7) + ((lane >> 4) * 8);
    const int kB8 = ((lane >> 3) & 1) * 8;
    const int er = lane >> 2;
    const int ec = (lane & 3) * 2;

    // F: 2m x 4n(16); IOU: 2m x 4n(8 cols x 3 gates)
    const int fwm = (wid & 1) * 16, fwn = (wid >> 1) * 16;
    const int iwm = (wid & 1) * 16, iwn = wid >> 1;

    uint32_t adAF = smbase + ((fwm + rA) * SA + kA8) * 2;
    uint32_t adBF = smbase + oUf + ((fwn + rB) * SA + kB8) * 2;
    uint32_t adAI = smbase + ((iwm + rA) * SA + kA8) * 2;
    uint32_t adBI4 = smbase + oUi + ((iwn * 24 + rB) * SA + kB8) * 2;
    uint32_t adBI2 = smbase + oUi
                   + ((iwn * 24 + 16 + (lane & 7)) * SA + kB8) * 2;

    int slot = 0;
    for (int dd = 9; dd >= 0; dd--) {
        const int cs = dd + 1;
        const int CHm1 = (1 << cs) - 1;
        const int Pm1 = (1 << dd) - 1;
        const int uF = (NT << cs) >> 5;
        const int uI = (NT << dd) >> 5;

        // ================= F phase =================
        for (int u = (bid >> 1); u < uF; u += (G >> 1)) {
            __syncthreads();
#pragma unroll
            for (int s = 0; s < 4; s++) {
                int j = tid + s * 256;
                int r = j >> 5, kq = j & 31;
                int L = u * 32 + r;
                int t = L >> cs, rr = L & CHm1;
                int gc = t * MT + CHm1 + rr;
                float4 v = *(const float4*)&h[gc * 128 + kq * 4];
                split_store4(v, &As_h[r * SA + kq * 4], &As_l[r * SA + kq * 4]);
            }
            __syncthreads();

            float acc[2][4];
#pragma unroll
            for (int j = 0; j < 2; j++)
#pragma unroll
                for (int k = 0; k < 4; k++) acc[j][k] = 0.0f;
#pragma unroll
            for (int kc = 0; kc < 8; kc++) {
                const uint32_t ko = kc * 32;
                uint32_t a_h[4], a_l[4], b_h[4], b_l[4];
                ldsm4(adAF + ko, a_h);
                ldsm4(adAF + oAsl + ko, a_l);
                ldsm4(adBF + ko, b_h);
                ldsm4(adBF + oUfD + ko, b_l);
#pragma unroll
                for (int nt = 0; nt < 2; nt++) {
                    mma16816(acc[nt], a_h, b_h[nt * 2], b_h[nt * 2 + 1]);
                    mma16816(acc[nt], a_l, b_h[nt * 2], b_h[nt * 2 + 1]);
                    mma16816(acc[nt], a_h, b_l[nt * 2], b_l[nt * 2 + 1]);
                }
            }
#pragma unroll
            for (int nt = 0; nt < 2; nt++) {
                int col = colhalf * 64 + fwn + nt * 8 + ec;
#pragma unroll
                for (int half = 0; half < 2; half++) {
                    int lr = fwm + er + half * 8;
                    int L = u * 32 + lr;
                    int t = L >> cs, rr = L & CHm1;
                    int gc = t * MT + CHm1 + rr;
                    int gp = t * MT + Pm1 + (rr >> 1);
                    float2 wf = *(const float2*)&g_wxf[gp * 128 + col];
                    float2 cc = *(const float2*)&g_c[gc * 128 + col];
                    float2 o;
                    o.x = sigf(acc[nt][half * 2 + 0] + wf.x) * cc.x;
                    o.y = sigf(acc[nt][half * 2 + 1] + wf.y) * cc.y;
                    *(float2*)&g_fc[gc * 128 + col] = o;
                }
            }
        }
        gbar(slot++, G);

        // ================= IOU phase =================
        for (int u = (bid >> 2); u < uI; u += (G >> 2)) {
            __syncthreads();
#pragma unroll
            for (int s = 0; s < 4; s++) {
                int j = tid + s * 256;
                int r = j >> 5, kq = j & 31;
                int Lp = u * 32 + r;
                int t = Lp >> dd, rr = Lp & Pm1;
                int gc1 = t * MT + 2 * Pm1 + 1 + 2 * rr;
                float4 v1 = *(const float4*)&h[gc1 * 128 + kq * 4];
                float4 v2 = *(const float4*)&h[(gc1 + 1) * 128 + kq * 4];
                float4 v = make_float4(v1.x + v2.x, v1.y + v2.y,
                                       v1.z + v2.z, v1.w + v2.w);
                split_store4(v, &As_h[r * SA + kq * 4], &As_l[r * SA + kq * 4]);
            }
            __syncthreads();

            float acc[3][4];
#pragma unroll
            for (int j = 0; j < 3; j++)
#pragma unroll
                for (int k = 0; k < 4; k++) acc[j][k] = 0.0f;
#pragma unroll
            for (int kc = 0; kc < 8; kc++) {
                const uint32_t ko = kc * 32;
                uint32_t a_h[4], a_l[4], b_h[4], b_l[4], u_h[2], u_l[2];
                ldsm4(adAI + ko, a_h);
                ldsm4(adAI + oAsl + ko, a_l);
                ldsm4(adBI4 + ko, b_h);
                ldsm4(adBI4 + oUiD + ko, b_l);
                ldsm2(adBI2 + ko, u_h);
                ldsm2(adBI2 + oUiD + ko, u_l);
                // gate i
                mma16816(acc[0], a_h, b_h[0], b_h[1]);
                mma16816(acc[0], a_l, b_h[0], b_h[1]);
                mma16816(acc[0], a_h, b_l[0], b_l[1]);
                // gate o
                mma16816(acc[1], a_h, b_h[2], b_h[3]);
                mma16816(acc[1], a_l, b_h[2], b_h[3]);
                mma16816(acc[1], a_h, b_l[2], b_l[3]);
                // gate u
                mma16816(acc[2], a_h, u_h[0], u_h[1]);
                mma16816(acc[2], a_l, u_h[0], u_h[1]);
                mma16816(acc[2], a_h, u_l[0], u_l[1]);
            }
            {
                int col = colgrp * 32 + iwn * 8 + ec;
#pragma unroll
                for (int half = 0; half < 2; half++) {
                    int pr = iwm + er + half * 8;
                    int Lp = u * 32 + pr;
                    int t = Lp >> dd, rr = Lp & Pm1;
                    int gp = t * MT + Pm1 + rr;
                    int gc1 = t * MT + 2 * Pm1 + 1 + 2 * rr;
                    float2 wi = *(const float2*)&g_wxiou[gp * D3 + col];
                    float2 wo = *(const float2*)&g_wxiou[gp * D3 + 128 + col];
                    float2 wu = *(const float2*)&g_wxiou[gp * D3 + 256 + col];
                    float2 f1 = *(const float2*)&g_fc[gc1 * 128 + col];
                    float2 f2 = *(const float2*)&g_fc[(gc1 + 1) * 128 + col];
                    float i0 = acc[0][half * 2 + 0] + wi.x;
                    float i1 = acc[0][half * 2 + 1] + wi.y;
                    float o0 = acc[1][half * 2 + 0] + wo.x;
                    float o1 = acc[1][half * 2 + 1] + wo.y;
                    float u0 = acc[2][half * 2 + 0] + wu.x;
                    float u1 = acc[2][half * 2 + 1] + wu.y;
                    float2 cres, hres;
                    float cn0 = sigf(i0) * tanhfast(u0) + f1.x + f2.x;
                    float cn1 = sigf(i1) * tanhfast(u1) + f1.y + f2.y;
                    cres.x = cn0; cres.y = cn1;
                    hres.x = sigf(o0) * tanhfast(cn0);
                    hres.y = sigf(o1) * tanhfast(cn1);
                    *(float2*)&g_c[gp * 128 + col] = cres;
                    *(float2*)&h[gp * 128 + col] = hres;
                }
            }
        }
        if (dd > 0) gbar(slot++, G);
    }
}

// ---------------------------------------------------------------------------
extern "C" void kernel_launch(void* const* d_in, const int* in_sizes, int n_in,
                              void* d_out, int out_size)
{
    const float* features = (const float*)d_in[0];
    const float* W_iou    = (const float*)d_in[1];
    const float* b_iou    = (const float*)d_in[2];
    const float* U_iou    = (const float*)d_in[3];
    const float* W_f      = (const float*)d_in[4];
    const float* b_f      = (const float*)d_in[5];
    const float* U_f      = (const float*)d_in[6];
    float* h = (float*)d_out;

    (void)cudaFuncSetAttribute(k_wxiou, cudaFuncAttributeMaxDynamicSharedMemorySize, WX_SMEM);
    (void)cudaFuncSetAttribute(k_wxf, cudaFuncAttributeMaxDynamicSharedMemorySize, G128_SMEM);
    (void)cudaFuncSetAttribute(k_levels, cudaFuncAttributeMaxDynamicSharedMemorySize, LV_SMEM);

    int nsm = 148, occ = 1;
    (void)cudaDeviceGetAttribute(&nsm, cudaDevAttrMultiProcessorCount, 0);
    (void)cudaOccupancyMaxActiveBlocksPerMultiprocessor(&occ, k_levels, 256, LV_SMEM);
    if (occ < 1) occ = 1;
    if (occ > 2) occ = 2;
    int G = (nsm * occ) & ~3;   // multiple of 4 for col-group striding
    if (G < 4) G = 4;

    k_cvt<<<192, 256>>>(W_iou, U_iou, W_f, U_f);   // also resets g_counts
    k_wxiou<<<dim3(1024, 4), 128, WX_SMEM>>>(features, b_iou, h);
    k_wxf<<<512, 256, G128_SMEM>>>(features, b_f);
    k_levels<<<G, 256, LV_SMEM>>>(h, G);
}

// round 12
// speedup vs baseline: 1.3961x; 1.0071x over previous
#include <cuda_runtime.h>
#include <cuda_bf16.h>
#include <cstdint>

#define D3 384
#define MT 2047          // nodes per tree
#define NT 32
#define NN 65504         // 32 * 2047
#define NINT 32736       // 32 * 1023 internal nodes
#define SA 136           // smem row stride in bf16 (272B) -> ldmatrix conflict-free

// ------------------------- device scratch ----------------------------------
__device__ float g_wxiou[NN * D3];      // W_iou*x + b_iou (internal nodes only)
__device__ float g_wxf[NN * 128];       // W_f*x + b_f, internal nodes
__device__ float g_c[NN * 128];         // cell state
__device__ float g_fc[NN * 128];        // f(child)*c(child)
__device__ unsigned g_counts[32];       // global barrier slots (reset by k_cvt)

__device__ __align__(16) __nv_bfloat16 g_Wiou_h[D3 * 128];
__device__ __align__(16) __nv_bfloat16 g_Wiou_l[D3 * 128];
__device__ __align__(16) __nv_bfloat16 g_Uiou_h[D3 * 128];
__device__ __align__(16) __nv_bfloat16 g_Uiou_l[D3 * 128];
__device__ __align__(16) __nv_bfloat16 g_Wf_h[128 * 128];
__device__ __align__(16) __nv_bfloat16 g_Wf_l[128 * 128];
__device__ __align__(16) __nv_bfloat16 g_Uf_h[128 * 128];
__device__ __align__(16) __nv_bfloat16 g_Uf_l[128 * 128];

__device__ __forceinline__ float sigf(float x) {
    return 1.0f / (1.0f + __expf(-x));
}
__device__ __forceinline__ float tanhfast(float x) {
    return 1.0f - 2.0f / (__expf(2.0f * x) + 1.0f);
}

// ------------------------- mma / ldmatrix helpers ---------------------------
__device__ __forceinline__ void ldsm4(uint32_t addr, uint32_t* r) {
    asm volatile("ldmatrix.sync.aligned.m8n8.x4.shared.b16 {%0,%1,%2,%3}, [%4];"
                 : "=r"(r[0]), "=r"(r[1]), "=r"(r[2]), "=r"(r[3]) : "r"(addr));
}
__device__ __forceinline__ void ldsm2(uint32_t addr, uint32_t* r) {
    asm volatile("ldmatrix.sync.aligned.m8n8.x2.shared.b16 {%0,%1}, [%2];"
                 : "=r"(r[0]), "=r"(r[1]) : "r"(addr));
}
__device__ __forceinline__ void mma16816(float* c, const uint32_t* a,
                                         uint32_t b0, uint32_t b1) {
    asm volatile(
        "mma.sync.aligned.m16n8k16.row.col.f32.bf16.bf16.f32 "
        "{%0,%1,%2,%3}, {%4,%5,%6,%7}, {%8,%9}, {%0,%1,%2,%3};"
        : "+f"(c[0]), "+f"(c[1]), "+f"(c[2]), "+f"(c[3])
        : "r"(a[0]), "r"(a[1]), "r"(a[2]), "r"(a[3]), "r"(b0), "r"(b1));
}
__device__ __forceinline__ void split1(float v, __nv_bfloat16& h, __nv_bfloat16& l) {
    h = __float2bfloat16(v);
    l = __float2bfloat16(v - __bfloat162float(h));
}
__device__ __forceinline__ void split_store4(float4 v, __nv_bfloat16* dh,
                                             __nv_bfloat16* dl) {
    __nv_bfloat16 h0, h1, h2, h3, l0, l1, l2, l3;
    split1(v.x, h0, l0); split1(v.y, h1, l1);
    split1(v.z, h2, l2); split1(v.w, h3, l3);
    __nv_bfloat162 p;
    p.x = h0; p.y = h1; ((__nv_bfloat162*)dh)[0] = p;
    p.x = h2; p.y = h3; ((__nv_bfloat162*)dh)[1] = p;
    p.x = l0; p.y = l1; ((__nv_bfloat162*)dl)[0] = p;
    p.x = l2; p.y = l3; ((__nv_bfloat162*)dl)[1] = p;
}

// ------------------------- weight split kernel (+ barrier reset) ------------
__global__ void k_cvt(const float* __restrict__ Wiou, const float* __restrict__ Uiou,
                      const float* __restrict__ Wf, const float* __restrict__ Uf)
{
    if (blockIdx.x == 0 && threadIdx.x < 32) g_counts[threadIdx.x] = 0;
    int idx = blockIdx.x * 256 + threadIdx.x;     // 384*128
    int n = idx >> 7, k = idx & 127;
    split1(Wiou[k * D3 + n], g_Wiou_h[n * 128 + k], g_Wiou_l[n * 128 + k]);
    split1(Uiou[k * D3 + n], g_Uiou_h[n * 128 + k], g_Uiou_l[n * 128 + k]);
    if (n < 128) {
        split1(Wf[k * 128 + n], g_Wf_h[n * 128 + k], g_Wf_l[n * 128 + k]);
        split1(Uf[k * 128 + n], g_Uf_h[n * 128 + k], g_Uf_l[n * 128 + k]);
    }
}

// ------------------------- wxiou GEMM, gate-interleaved + leaf fused --------
#define WX_SMEM ((2 * 64 + 2 * 96) * SA * 2)   // 87,040 B
__global__ __launch_bounds__(128) void k_wxiou(const float* __restrict__ Asrc,
                                               const float* __restrict__ bias,
                                               float* __restrict__ hout)
{
    extern __shared__ __nv_bfloat16 sm[];
    __nv_bfloat16* As_h = sm;
    __nv_bfloat16* As_l = sm + 64 * SA;
    __nv_bfloat16* Bs_h = sm + 128 * SA;
    __nv_bfloat16* Bs_l = sm + (128 + 96) * SA;

    const int tid = threadIdx.x;
    const int row0 = blockIdx.x * 64;
    const int nb = blockIdx.y;     // 0..3: within-gate col block of 32

    for (int j = tid; j < 96 * 16; j += 128) {
        int lr = j >> 4, q = j & 15;
        int o = lr / 24, rem = lr - o * 24;
        int s = rem >> 3, jj = rem & 7;
        int n = nb * 32 + o * 8 + jj + s * 128;
        *(uint4*)&Bs_h[lr * SA + q * 8] = *(const uint4*)&g_Wiou_h[n * 128 + q * 8];
        *(uint4*)&Bs_l[lr * SA + q * 8] = *(const uint4*)&g_Wiou_l[n * 128 + q * 8];
    }
#pragma unroll
    for (int s = 0; s < 16; s++) {
        int j = tid + s * 128;
        int r = j >> 5, kq = j & 31;
        int L = row0 + r;
        int g = (L < NN) ? L : NN - 1;
        float4 v = *(const float4*)&Asrc[g * 128 + kq * 4];
        split_store4(v, &As_h[r * SA + kq * 4], &As_l[r * SA + kq * 4]);
    }
    __syncthreads();

    const int lane = tid & 31, wid = tid >> 5;
    const int wm = (wid & 1) * 32;
    const int wn = wid >> 1;       // 0..1 : two octets each

    float acc[2][6][4];
#pragma unroll
    for (int i = 0; i < 2; i++)
#pragma unroll
        for (int j = 0; j < 6; j++)
#pragma unroll
            for (int k = 0; k < 4; k++) acc[i][j][k] = 0.0f;

    const uint32_t smbase = (uint32_t)__cvta_generic_to_shared(sm);
    const uint32_t offAl = 64 * SA * 2;
    const uint32_t offBh = 128 * SA * 2;
    const uint32_t offBl = (128 + 96) * SA * 2;

    const int rA = lane & 15;
    const int kA8 = (lane >> 4) * 8;
    uint32_t adA0 = smbase + ((wm + rA) * SA + kA8) * 2;
    uint32_t adA1 = smbase + ((wm + 16 + rA) * SA + kA8) * 2;
    const int rB = (lane & 7) + ((lane >> 4) * 8);
    const int kB8 = ((lane >> 3) & 1) * 8;
    uint32_t adB[3];
#pragma unroll
    for (int i = 0; i < 3; i++)
        adB[i] = smbase + offBh + ((wn * 48 + i * 16 + rB) * SA + kB8) * 2;

#pragma unroll
    for (int kc = 0; kc < 8; kc++) {
        const uint32_t ko = kc * 32;
        uint32_t a_h[2][4], a_l[2][4], b_h[3][4], b_l[3][4];
        ldsm4(adA0 + ko, a_h[0]);
        ldsm4(adA1 + ko, a_h[1]);
        ldsm4(adA0 + offAl + ko, a_l[0]);
        ldsm4(adA1 + offAl + ko, a_l[1]);
#pragma unroll
        for (int i = 0; i < 3; i++) {
            ldsm4(adB[i] + ko, b_h[i]);
            ldsm4(adB[i] + (offBl - offBh) + ko, b_l[i]);
        }
#pragma unroll
        for (int mi = 0; mi < 2; mi++)
#pragma unroll
            for (int nt = 0; nt < 6; nt++) {
                uint32_t bh0 = b_h[nt >> 1][(nt & 1) * 2];
                uint32_t bh1 = b_h[nt >> 1][(nt & 1) * 2 + 1];
                uint32_t bl0 = b_l[nt >> 1][(nt & 1) * 2];
                uint32_t bl1 = b_l[nt >> 1][(nt & 1) * 2 + 1];
                mma16816(acc[mi][nt], a_h[mi], bh0, bh1);
                mma16816(acc[mi][nt], a_l[mi], bh0, bh1);
                mma16816(acc[mi][nt], a_h[mi], bl0, bl1);
            }
    }

    const int er = lane >> 2;
    const int ec = (lane & 3) * 2;
#pragma unroll
    for (int mi = 0; mi < 2; mi++)
#pragma unroll
        for (int ol = 0; ol < 2; ol++) {
            int col = nb * 32 + (2 * wn + ol) * 8 + ec;
            int a0 = ol * 3;
#pragma unroll
            for (int half = 0; half < 2; half++) {
                int L = row0 + wm + mi * 16 + er + half * 8;
                if (L >= NN) continue;
                int t = L / MT;
                int rr = L - t * MT;
                float i0 = acc[mi][a0 + 0][half * 2 + 0] + bias[col];
                float i1 = acc[mi][a0 + 0][half * 2 + 1] + bias[col + 1];
                float o0 = acc[mi][a0 + 1][half * 2 + 0] + bias[128 + col];
                float o1 = acc[mi][a0 + 1][half * 2 + 1] + bias[128 + col + 1];
                float u0 = acc[mi][a0 + 2][half * 2 + 0] + bias[256 + col];
                float u1 = acc[mi][a0 + 2][half * 2 + 1] + bias[256 + col + 1];
                if (rr >= 1023) {
                    float2 cv, hv;
                    float cn0 = sigf(i0) * tanhfast(u0);
                    float cn1 = sigf(i1) * tanhfast(u1);
                    cv.x = cn0; cv.y = cn1;
                    hv.x = sigf(o0) * tanhfast(cn0);
                    hv.y = sigf(o1) * tanhfast(cn1);
                    *(float2*)&g_c[L * 128 + col] = cv;
                    *(float2*)&hout[L * 128 + col] = hv;
                } else {
                    float2 a;
                    a.x = i0; a.y = i1;
                    *(float2*)&g_wxiou[L * D3 + col] = a;
                    a.x = o0; a.y = o1;
                    *(float2*)&g_wxiou[L * D3 + 128 + col] = a;
                    a.x = u0; a.y = u1;
                    *(float2*)&g_wxiou[L * D3 + 256 + col] = a;
                }
            }
        }
}

// ------------------------- wxf precompute GEMM (N=128 resident) -------------
#define G128_SMEM ((2 * 64 + 2 * 128) * SA * 2)
__global__ __launch_bounds__(256) void k_wxf(const float* __restrict__ Asrc,
                                             const float* __restrict__ bias)
{
    extern __shared__ __nv_bfloat16 sm[];
    __nv_bfloat16* As_h = sm;
    __nv_bfloat16* As_l = sm + 64 * SA;
    __nv_bfloat16* Bs_h = sm + 2 * 64 * SA;
    __nv_bfloat16* Bs_l = sm + (2 * 64 + 128) * SA;

    const int tid = threadIdx.x;
    const int L0 = blockIdx.x * 64;

#pragma unroll
    for (int s = 0; s < 8; s++) {
        int j = tid + s * 256;
        int r = j >> 4, q = j & 15;
        *(uint4*)&Bs_h[r * SA + q * 8] = *(const uint4*)&g_Wf_h[r * 128 + q * 8];
        *(uint4*)&Bs_l[r * SA + q * 8] = *(const uint4*)&g_Wf_l[r * 128 + q * 8];
    }
#pragma unroll
    for (int s = 0; s < 8; s++) {
        int j = tid + s * 256;
        int r = j >> 5, kq = j & 31;
        int L = L0 + r;
        int Lc = (L < NINT) ? L : NINT - 1;
        int t = Lc / 1023;
        int g = t * MT + (Lc - t * 1023);
        float4 v = *(const float4*)&Asrc[g * 128 + kq * 4];
        split_store4(v, &As_h[r * SA + kq * 4], &As_l[r * SA + kq * 4]);
    }
    __syncthreads();

    const int lane = tid & 31, wid = tid >> 5;
    const int wm = (wid & 1) * 32, wn = (wid >> 1) * 32;

    float acc[2][4][4];
#pragma unroll
    for (int i = 0; i < 2; i++)
#pragma unroll
        for (int j = 0; j < 4; j++)
#pragma unroll
            for (int k = 0; k < 4; k++) acc[i][j][k] = 0.0f;

    const uint32_t smbase = (uint32_t)__cvta_generic_to_shared(sm);
    const uint32_t offAl = 64 * SA * 2;
    const uint32_t offBh = 2 * 64 * SA * 2;
    const uint32_t offBl = (2 * 64 + 128) * SA * 2;

    const int rA = lane & 15;
    const int kA8 = (lane >> 4) * 8;
    uint32_t adA0 = smbase + ((wm + rA) * SA + kA8) * 2;
    uint32_t adA1 = smbase + ((wm + 16 + rA) * SA + kA8) * 2;
    const int rB = (lane & 7) + ((lane >> 4) * 8);
    const int kB8 = ((lane >> 3) & 1) * 8;
    uint32_t adB0 = smbase + offBh + ((wn + rB) * SA + kB8) * 2;
    uint32_t adB1 = smbase + offBh + ((wn + 16 + rB) * SA + kB8) * 2;

#pragma unroll
    for (int kc = 0; kc < 8; kc++) {
        const uint32_t ko = kc * 32;
        uint32_t a_h[2][4], a_l[2][4], b_h[2][4], b_l[2][4];
        ldsm4(adA0 + ko, a_h[0]);
        ldsm4(adA1 + ko, a_h[1]);
        ldsm4(adA0 + offAl + ko, a_l[0]);
        ldsm4(adA1 + offAl + ko, a_l[1]);
        ldsm4(adB0 + ko, b_h[0]);
        ldsm4(adB1 + ko, b_h[1]);
        ldsm4(adB0 + (offBl - offBh) + ko, b_l[0]);
        ldsm4(adB1 + (offBl - offBh) + ko, b_l[1]);
#pragma unroll
        for (int mi = 0; mi < 2; mi++)
#pragma unroll
            for (int nt = 0; nt < 4; nt++) {
                uint32_t bh0 = b_h[nt >> 1][(nt & 1) * 2];
                uint32_t bh1 = b_h[nt >> 1][(nt & 1) * 2 + 1];
                uint32_t bl0 = b_l[nt >> 1][(nt & 1) * 2];
                uint32_t bl1 = b_l[nt >> 1][(nt & 1) * 2 + 1];
                mma16816(acc[mi][nt], a_h[mi], bh0, bh1);
                mma16816(acc[mi][nt], a_l[mi], bh0, bh1);
                mma16816(acc[mi][nt], a_h[mi], bl0, bl1);
            }
    }

    const int er = lane >> 2;
    const int ec = (lane & 3) * 2;
#pragma unroll
    for (int mi = 0; mi < 2; mi++)
#pragma unroll
        for (int nt = 0; nt < 4; nt++) {
            int n = wn + nt * 8 + ec;
#pragma unroll
            for (int half = 0; half < 2; half++) {
                int L = L0 + wm + mi * 16 + er + half * 8;
                if (L < NINT) {
                    int t = L / 1023;
                    int g = t * MT + (L - t * 1023);
                    float2 o;
                    o.x = acc[mi][nt][half * 2 + 0] + bias[n];
                    o.y = acc[mi][nt][half * 2 + 1] + bias[n + 1];
                    *(float2*)&g_wxf[g * 128 + n] = o;
                }
            }
        }
}

// ------------------------- persistent level kernel (resident B) -------------
// Each CTA keeps resident: Uf col-half (bid&1, 64 cols) + Uiou gate-interleaved
// col-group (bid&3: 32 within-gate cols -> 96 rows). Per level:
//   F phase: items = 32-child row units x 2 colhalves -> g_fc;  gbar
//   IOU phase: items = 32-parent row units x 4 colgroups -> full cell; gbar
#define LV_SMEM (384 * SA * 2)   // As(2*32) + Uf(2*64) + Ui(2*96) = 104,448 B

__device__ __forceinline__ void gbar(int slot, int G) {
    __threadfence();
    __syncthreads();
    if (threadIdx.x == 0) {
        atomicAdd(&g_counts[slot], 1u);
        while (atomicAdd(&g_counts[slot], 0u) < (unsigned)G) __nanosleep(64);
    }
    __syncthreads();
}

__global__ __launch_bounds__(256, 2) void k_levels(float* __restrict__ h, int G)
{
    extern __shared__ __nv_bfloat16 sm[];
    const int tid = threadIdx.x, lane = tid & 31, wid = tid >> 5;
    const int bid = blockIdx.x;
    const int colhalf = bid & 1;
    const int colgrp = bid & 3;

    __nv_bfloat16* As_h = sm;                 // 32 rows
    __nv_bfloat16* As_l = sm + 32 * SA;
    __nv_bfloat16* Uf_hS = sm + 64 * SA;      // 64 rows
    __nv_bfloat16* Uf_lS = sm + 128 * SA;
    __nv_bfloat16* Ui_hS = sm + 192 * SA;     // 96 rows
    __nv_bfloat16* Ui_lS = sm + 288 * SA;

    // ---- resident B loads (once per kernel) ----
    for (int j = tid; j < 64 * 16; j += 256) {
        int r = j >> 4, q = j & 15;
        int n = colhalf * 64 + r;
        *(uint4*)&Uf_hS[r * SA + q * 8] = *(const uint4*)&g_Uf_h[n * 128 + q * 8];
        *(uint4*)&Uf_lS[r * SA + q * 8] = *(const uint4*)&g_Uf_l[n * 128 + q * 8];
    }
    for (int j = tid; j < 96 * 16; j += 256) {
        int lr = j >> 4, q = j & 15;
        int wn = lr / 24, rem = lr - wn * 24;
        int gate = rem >> 3, jj = rem & 7;
        int n = gate * 128 + colgrp * 32 + wn * 8 + jj;
        *(uint4*)&Ui_hS[lr * SA + q * 8] = *(const uint4*)&g_Uiou_h[n * 128 + q * 8];
        *(uint4*)&Ui_lS[lr * SA + q * 8] = *(const uint4*)&g_Uiou_l[n * 128 + q * 8];
    }
    __syncthreads();

    const uint32_t smbase = (uint32_t)__cvta_generic_to_shared(sm);
    const uint32_t oAsl = 32 * SA * 2;
    const uint32_t oUf = 64 * SA * 2;
    const uint32_t oUfD = 64 * SA * 2;    // Uf_l - Uf_h
    const uint32_t oUi = 192 * SA * 2;
    const uint32_t oUiD = 96 * SA * 2;    // Ui_l - Ui_h

    const int rA = lane & 15;
    const int kA8 = (lane >> 4) * 8;
    const int rB = (lane & 7) + ((lane >> 4) * 8);
    const int kB8 = ((lane >> 3) & 1) * 8;
    const int er = lane >> 2;
    const int ec = (lane & 3) * 2;

    // F: 2m x 4n(16); IOU: 2m x 4n(8 cols x 3 gates)
    const int fwm = (wid & 1) * 16, fwn = (wid >> 1) * 16;
    const int iwm = (wid & 1) * 16, iwn = wid >> 1;

    uint32_t adAF = smbase + ((fwm + rA) * SA + kA8) * 2;
    uint32_t adBF = smbase + oUf + ((fwn + rB) * SA + kB8) * 2;
    uint32_t adAI = smbase + ((iwm + rA) * SA + kA8) * 2;
    uint32_t adBI4 = smbase + oUi + ((iwn * 24 + rB) * SA + kB8) * 2;
    uint32_t adBI2 = smbase + oUi
                   + ((iwn * 24 + 16 + (lane & 7)) * SA + kB8) * 2;

    int slot = 0;
    for (int dd = 9; dd >= 0; dd--) {
        const int cs = dd + 1;
        const int CHm1 = (1 << cs) - 1;
        const int Pm1 = (1 << dd) - 1;
        const int uF = (NT << cs) >> 5;
        const int uI = (NT << dd) >> 5;

        // ================= F phase =================
        for (int u = (bid >> 1); u < uF; u += (G >> 1)) {
            __syncthreads();
#pragma unroll
            for (int s = 0; s < 4; s++) {
                int j = tid + s * 256;
                int r = j >> 5, kq = j & 31;
                int L = u * 32 + r;
                int t = L >> cs, rr = L & CHm1;
                int gc = t * MT + CHm1 + rr;
                float4 v = *(const float4*)&h[gc * 128 + kq * 4];
                split_store4(v, &As_h[r * SA + kq * 4], &As_l[r * SA + kq * 4]);
            }
            __syncthreads();

            float acc[2][4];
#pragma unroll
            for (int j = 0; j < 2; j++)
#pragma unroll
                for (int k = 0; k < 4; k++) acc[j][k] = 0.0f;
#pragma unroll
            for (int kc = 0; kc < 8; kc++) {
                const uint32_t ko = kc * 32;
                uint32_t a_h[4], a_l[4], b_h[4], b_l[4];
                ldsm4(adAF + ko, a_h);
                ldsm4(adAF + oAsl + ko, a_l);
                ldsm4(adBF + ko, b_h);
                ldsm4(adBF + oUfD + ko, b_l);
#pragma unroll
                for (int nt = 0; nt < 2; nt++) {
                    mma16816(acc[nt], a_h, b_h[nt * 2], b_h[nt * 2 + 1]);
                    mma16816(acc[nt], a_l, b_h[nt * 2], b_h[nt * 2 + 1]);
                    mma16816(acc[nt], a_h, b_l[nt * 2], b_l[nt * 2 + 1]);
                }
            }
#pragma unroll
            for (int nt = 0; nt < 2; nt++) {
                int col = colhalf * 64 + fwn + nt * 8 + ec;
#pragma unroll
                for (int half = 0; half < 2; half++) {
                    int lr = fwm + er + half * 8;
                    int L = u * 32 + lr;
                    int t = L >> cs, rr = L & CHm1;
                    int gc = t * MT + CHm1 + rr;
                    int gp = t * MT + Pm1 + (rr >> 1);
                    float2 wf = *(const float2*)&g_wxf[gp * 128 + col];
                    float2 cc = *(const float2*)&g_c[gc * 128 + col];
                    float2 o;
                    o.x = sigf(acc[nt][half * 2 + 0] + wf.x) * cc.x;
                    o.y = sigf(acc[nt][half * 2 + 1] + wf.y) * cc.y;
                    *(float2*)&g_fc[gc * 128 + col] = o;
                }
            }
        }
        gbar(slot++, G);

        // ================= IOU phase =================
        for (int u = (bid >> 2); u < uI; u += (G >> 2)) {
            __syncthreads();
#pragma unroll
            for (int s = 0; s < 4; s++) {
                int j = tid + s * 256;
                int r = j >> 5, kq = j & 31;
                int Lp = u * 32 + r;
                int t = Lp >> dd, rr = Lp & Pm1;
                int gc1 = t * MT + 2 * Pm1 + 1 + 2 * rr;
                float4 v1 = *(const float4*)&h[gc1 * 128 + kq * 4];
                float4 v2 = *(const float4*)&h[(gc1 + 1) * 128 + kq * 4];
                float4 v = make_float4(v1.x + v2.x, v1.y + v2.y,
                                       v1.z + v2.z, v1.w + v2.w);
                split_store4(v, &As_h[r * SA + kq * 4], &As_l[r * SA + kq * 4]);
            }
            __syncthreads();

            float acc[3][4];
#pragma unroll
            for (int j = 0; j < 3; j++)
#pragma unroll
                for (int k = 0; k < 4; k++) acc[j][k] = 0.0f;
#pragma unroll
            for (int kc = 0; kc < 8; kc++) {
                const uint32_t ko = kc * 32;
                uint32_t a_h[4], a_l[4], b_h[4], b_l[4], u_h[2], u_l[2];
                ldsm4(adAI + ko, a_h);
                ldsm4(adAI + oAsl + ko, a_l);
                ldsm4(adBI4 + ko, b_h);
                ldsm4(adBI4 + oUiD + ko, b_l);
                ldsm2(adBI2 + ko, u_h);
                ldsm2(adBI2 + oUiD + ko, u_l);
                // gate i
                mma16816(acc[0], a_h, b_h[0], b_h[1]);
                mma16816(acc[0], a_l, b_h[0], b_h[1]);
                mma16816(acc[0], a_h, b_l[0], b_l[1]);
                // gate o
                mma16816(acc[1], a_h, b_h[2], b_h[3]);
                mma16816(acc[1], a_l, b_h[2], b_h[3]);
                mma16816(acc[1], a_h, b_l[2], b_l[3]);
                // gate u
                mma16816(acc[2], a_h, u_h[0], u_h[1]);
                mma16816(acc[2], a_l, u_h[0], u_h[1]);
                mma16816(acc[2], a_h, u_l[0], u_l[1]);
            }
            {
                int col = colgrp * 32 + iwn * 8 + ec;
#pragma unroll
                for (int half = 0; half < 2; half++) {
                    int pr = iwm + er + half * 8;
                    int Lp = u * 32 + pr;
                    int t = Lp >> dd, rr = Lp & Pm1;
                    int gp = t * MT + Pm1 + rr;
                    int gc1 = t * MT + 2 * Pm1 + 1 + 2 * rr;
                    float2 wi = *(const float2*)&g_wxiou[gp * D3 + col];
                    float2 wo = *(const float2*)&g_wxiou[gp * D3 + 128 + col];
                    float2 wu = *(const float2*)&g_wxiou[gp * D3 + 256 + col];
                    float2 f1 = *(const float2*)&g_fc[gc1 * 128 + col];
                    float2 f2 = *(const float2*)&g_fc[(gc1 + 1) * 128 + col];
                    float i0 = acc[0][half * 2 + 0] + wi.x;
                    float i1 = acc[0][half * 2 + 1] + wi.y;
                    float o0 = acc[1][half * 2 + 0] + wo.x;
                    float o1 = acc[1][half * 2 + 1] + wo.y;
                    float u0 = acc[2][half * 2 + 0] + wu.x;
                    float u1 = acc[2][half * 2 + 1] + wu.y;
                    float2 cres, hres;
                    float cn0 = sigf(i0) * tanhfast(u0) + f1.x + f2.x;
                    float cn1 = sigf(i1) * tanhfast(u1) + f1.y + f2.y;
                    cres.x = cn0; cres.y = cn1;
                    hres.x = sigf(o0) * tanhfast(cn0);
                    hres.y = sigf(o1) * tanhfast(cn1);
                    *(float2*)&g_c[gp * 128 + col] = cres;
                    *(float2*)&h[gp * 128 + col] = hres;
                }
            }
        }
        if (dd > 0) gbar(slot++, G);
    }
}

// ---------------------------------------------------------------------------
extern "C" void kernel_launch(void* const* d_in, const int* in_sizes, int n_in,
                              void* d_out, int out_size)
{
    const float* features = (const float*)d_in[0];
    const float* W_iou    = (const float*)d_in[1];
    const float* b_iou    = (const float*)d_in[2];
    const float* U_iou    = (const float*)d_in[3];
    const float* W_f      = (const float*)d_in[4];
    const float* b_f      = (const float*)d_in[5];
    const float* U_f      = (const float*)d_in[6];
    float* h = (float*)d_out;

    (void)cudaFuncSetAttribute(k_wxiou, cudaFuncAttributeMaxDynamicSharedMemorySize, WX_SMEM);
    (void)cudaFuncSetAttribute(k_wxf, cudaFuncAttributeMaxDynamicSharedMemorySize, G128_SMEM);
    (void)cudaFuncSetAttribute(k_levels, cudaFuncAttributeMaxDynamicSharedMemorySize, LV_SMEM);

    int nsm = 148, occ = 1;
    (void)cudaDeviceGetAttribute(&nsm, cudaDevAttrMultiProcessorCount, 0);
    (void)cudaOccupancyMaxActiveBlocksPerMultiprocessor(&occ, k_levels, 256, LV_SMEM);
    if (occ < 1) occ = 1;
    if (occ > 2) occ = 2;
    int G = (nsm * occ) & ~3;   // multiple of 4 for col-group striding
    if (G < 4) G = 4;

    k_cvt<<<192, 256>>>(W_iou, U_iou, W_f, U_f);   // also resets g_counts
    k_wxiou<<<dim3(1024, 4), 128, WX_SMEM>>>(features, b_iou, h);
    k_wxf<<<512, 256, G128_SMEM>>>(features, b_f);
    k_levels<<<G, 256, LV_SMEM>>>(h, G);
}